// round 2
// baseline (speedup 1.0000x reference)
#include <cuda_runtime.h>

#define BATCH 1024

// ---------------- scratch (static device globals; no allocation) ----------------
__device__ float g_h1[BATCH * 32 * 20 * 20];   // conv1 out  [b][32][20][20]
__device__ float g_h2[BATCH * 64 * 9 * 9];     // conv2 out  [b][64][9][9]
__device__ float g_h3[BATCH * 3136];           // conv3 out flattened [b][c*49+y*7+x]
__device__ float g_h4[BATCH * 512];            // fc1 out    [b][512]

// =====================================================================
// conv1: x[b][4][84][84] -> h1[b][32][20][20], k=8, stride=4, + bias, relu
// 1 image per block. smem: input phase-decomposed (x%4), weights [k][oc].
// Thread (of 400): 8 output channels x 4 output rows at fixed ox.
// =====================================================================
__global__ __launch_bounds__(512) void conv1_kernel(
    const float* __restrict__ x, const float* __restrict__ w,
    const float* __restrict__ bias)
{
    extern __shared__ float sm[];
    float* in_s = sm;            // 4*84*4*21 = 28224 floats
    float* w_s  = sm + 28224;    // 256*32    =  8192 floats

    const int b   = blockIdx.x;
    const int tid = threadIdx.x;

    // load input with phase decomposition: in_s[((ic*84+y)*4 + x%4)*21 + x/4]
    const float* xg = x + b * 28224;
    for (int idx = tid; idx < 28224; idx += blockDim.x) {
        int ic  = idx / 7056;
        int rem = idx - ic * 7056;
        int y   = rem / 84;
        int xx  = rem - y * 84;
        in_s[((ic * 84 + y) * 4 + (xx & 3)) * 21 + (xx >> 2)] = xg[idx];
    }
    // weights: global [oc][ic][ky][kx] -> smem [k][oc], k = (ic*8+ky)*8+kx
    for (int idx = tid; idx < 8192; idx += blockDim.x) {
        int oc = idx >> 8;
        int k  = idx & 255;
        w_s[k * 32 + oc] = w[idx];
    }
    __syncthreads();

    if (tid < 400) {
        const int ocg = tid / 100;
        const int sp  = tid - ocg * 100;
        const int ox  = sp % 20;
        const int oyB = (sp / 20) * 4;   // 4 consecutive output rows

        float acc[8][4];
        #pragma unroll
        for (int j = 0; j < 8; j++)
            #pragma unroll
            for (int i = 0; i < 4; i++) acc[j][i] = 0.f;

        for (int ic = 0; ic < 4; ic++) {
            for (int ky = 0; ky < 8; ky++) {
                int rb[4];
                #pragma unroll
                for (int i = 0; i < 4; i++)
                    rb[i] = ((ic * 84 + (oyB + i) * 4 + ky) * 4) * 21 + ox;
                const int kbase = (ic * 8 + ky) * 8;
                #pragma unroll
                for (int kx = 0; kx < 8; kx++) {
                    float iv[4];
                    #pragma unroll
                    for (int i = 0; i < 4; i++)
                        iv[i] = in_s[rb[i] + (kx & 3) * 21 + (kx >> 2)];
                    const float4* wp = reinterpret_cast<const float4*>(
                        w_s + (kbase + kx) * 32 + ocg * 8);
                    float4 wa = wp[0], wb = wp[1];
                    #pragma unroll
                    for (int i = 0; i < 4; i++) {
                        acc[0][i] += wa.x * iv[i];
                        acc[1][i] += wa.y * iv[i];
                        acc[2][i] += wa.z * iv[i];
                        acc[3][i] += wa.w * iv[i];
                        acc[4][i] += wb.x * iv[i];
                        acc[5][i] += wb.y * iv[i];
                        acc[6][i] += wb.z * iv[i];
                        acc[7][i] += wb.w * iv[i];
                    }
                }
            }
        }
        float* ob = g_h1 + b * 12800;
        #pragma unroll
        for (int j = 0; j < 8; j++) {
            float bb = bias[ocg * 8 + j];
            #pragma unroll
            for (int i = 0; i < 4; i++) {
                float v = acc[j][i] + bb;
                ob[(ocg * 8 + j) * 400 + (oyB + i) * 20 + ox] = fmaxf(v, 0.f);
            }
        }
    }
}

// =====================================================================
// conv2: h1[b][32][20][20] -> h2[b][64][9][9], k=4, stride=2, + bias, relu
// 1 image per block. Input phase-decomposed (x%2). Thread (of 216): 8 oc x 3 rows.
// =====================================================================
__global__ __launch_bounds__(256) void conv2_kernel(
    const float* __restrict__ w, const float* __restrict__ bias)
{
    extern __shared__ float sm[];
    float* in_s = sm;            // 32*20*2*10 = 12800 floats
    float* w_s  = sm + 12800;    // 512*64     = 32768 floats

    const int b   = blockIdx.x;
    const int tid = threadIdx.x;

    const float* xg = g_h1 + b * 12800;
    for (int idx = tid; idx < 12800; idx += blockDim.x) {
        int c   = idx / 400;
        int rem = idx - c * 400;
        int y   = rem / 20;
        int xx  = rem - y * 20;
        in_s[((c * 20 + y) * 2 + (xx & 1)) * 10 + (xx >> 1)] = xg[idx];
    }
    // weights: global [oc][c][ky][kx] -> smem [k][oc], k = (c*4+ky)*4+kx
    for (int idx = tid; idx < 32768; idx += blockDim.x) {
        int oc = idx >> 9;
        int k  = idx & 511;
        w_s[k * 64 + oc] = w[idx];
    }
    __syncthreads();

    if (tid < 216) {
        const int ocg = tid / 27;
        const int r   = tid - ocg * 27;
        const int oyg = r / 9;
        const int ox  = r - oyg * 9;

        float acc[8][3];
        #pragma unroll
        for (int j = 0; j < 8; j++)
            #pragma unroll
            for (int i = 0; i < 3; i++) acc[j][i] = 0.f;

        for (int c = 0; c < 32; c++) {
            #pragma unroll
            for (int ky = 0; ky < 4; ky++) {
                #pragma unroll
                for (int kx = 0; kx < 4; kx++) {
                    const int p  = kx & 1;
                    const int xq = ox + (kx >> 1);
                    float iv[3];
                    #pragma unroll
                    for (int i = 0; i < 3; i++) {
                        int y = (oyg * 3 + i) * 2 + ky;
                        iv[i] = in_s[((c * 20 + y) * 2 + p) * 10 + xq];
                    }
                    const int k = (c * 4 + ky) * 4 + kx;
                    const float4* wp = reinterpret_cast<const float4*>(
                        w_s + k * 64 + ocg * 8);
                    float4 wa = wp[0], wb = wp[1];
                    #pragma unroll
                    for (int i = 0; i < 3; i++) {
                        acc[0][i] += wa.x * iv[i];
                        acc[1][i] += wa.y * iv[i];
                        acc[2][i] += wa.z * iv[i];
                        acc[3][i] += wa.w * iv[i];
                        acc[4][i] += wb.x * iv[i];
                        acc[5][i] += wb.y * iv[i];
                        acc[6][i] += wb.z * iv[i];
                        acc[7][i] += wb.w * iv[i];
                    }
                }
            }
        }
        float* ob = g_h2 + b * 5184;
        #pragma unroll
        for (int j = 0; j < 8; j++) {
            float bb = bias[ocg * 8 + j];
            #pragma unroll
            for (int i = 0; i < 3; i++) {
                float v = acc[j][i] + bb;
                ob[(ocg * 8 + j) * 81 + (oyg * 3 + i) * 9 + ox] = fmaxf(v, 0.f);
            }
        }
    }
}

// =====================================================================
// conv3: h2[b][64][9][9] -> h3[b][3136], k=3, stride=1, + bias, relu
// 2 images per block. Thread (of 224): 4 oc x 7 rows at fixed ox.
// =====================================================================
__global__ __launch_bounds__(256) void conv3_kernel(
    const float* __restrict__ w, const float* __restrict__ bias)
{
    extern __shared__ float sm[];
    float* in_s = sm;            // 2 * 5200 = 10400 floats (padded img stride)
    float* w_s  = sm + 10400;    // 576*64   = 36864 floats

    const int b2  = blockIdx.x * 2;
    const int tid = threadIdx.x;

    for (int idx = tid; idx < 10368; idx += blockDim.x) {
        int img = idx / 5184;
        int rem = idx - img * 5184;
        in_s[img * 5200 + rem] = g_h2[(b2 + img) * 5184 + rem];
    }
    // weights: global [oc][c][ky][kx] -> smem [k][oc], k = c*9 + ky*3 + kx
    for (int idx = tid; idx < 36864; idx += blockDim.x) {
        int oc = idx / 576;
        int k  = idx - oc * 576;
        w_s[k * 64 + oc] = w[idx];
    }
    __syncthreads();

    if (tid < 224) {
        const int img = tid / 112;
        const int r   = tid - img * 112;
        const int ocg = r / 7;
        const int ox  = r - ocg * 7;
        const float* ib = in_s + img * 5200;

        float acc[4][7];
        #pragma unroll
        for (int j = 0; j < 4; j++)
            #pragma unroll
            for (int i = 0; i < 7; i++) acc[j][i] = 0.f;

        for (int c = 0; c < 64; c++) {
            const float* ic_base = ib + c * 81;
            #pragma unroll
            for (int ky = 0; ky < 3; ky++) {
                #pragma unroll
                for (int kx = 0; kx < 3; kx++) {
                    float iv[7];
                    #pragma unroll
                    for (int i = 0; i < 7; i++)
                        iv[i] = ic_base[(i + ky) * 9 + ox + kx];
                    const int k = c * 9 + ky * 3 + kx;
                    const float4* wp = reinterpret_cast<const float4*>(
                        w_s + k * 64 + ocg * 4);
                    float4 wa = wp[0];
                    #pragma unroll
                    for (int i = 0; i < 7; i++) {
                        acc[0][i] += wa.x * iv[i];
                        acc[1][i] += wa.y * iv[i];
                        acc[2][i] += wa.z * iv[i];
                        acc[3][i] += wa.w * iv[i];
                    }
                }
            }
        }
        float* ob = g_h3 + (b2 + img) * 3136;
        #pragma unroll
        for (int j = 0; j < 4; j++) {
            float bb = bias[ocg * 4 + j];
            #pragma unroll
            for (int i = 0; i < 7; i++) {
                float v = acc[j][i] + bb;
                ob[(ocg * 4 + j) * 49 + i * 7 + ox] = fmaxf(v, 0.f);
            }
        }
    }
}

// =====================================================================
// fc1: h3[1024][3136] @ lin1_w[512][3136]^T + b -> relu -> h4[1024][512]
// 64x64 block tile, 4x4 micro-tile, K-tile 32, transposed smem (pitch 65).
// =====================================================================
__global__ __launch_bounds__(256) void fc1_kernel(
    const float* __restrict__ W, const float* __restrict__ bias)
{
    __shared__ float As[32 * 65];
    __shared__ float Bs[32 * 65];

    const int bm  = blockIdx.y;
    const int bn  = blockIdx.x;
    const int tid = threadIdx.x;
    const int tx  = tid & 15;
    const int ty  = tid >> 4;

    float acc[4][4];
    #pragma unroll
    for (int i = 0; i < 4; i++)
        #pragma unroll
        for (int j = 0; j < 4; j++) acc[i][j] = 0.f;

    const float* Ag = g_h3 + (bm * 64) * 3136;
    const float* Wg = W + (bn * 64) * 3136;

    for (int k0 = 0; k0 < 3136; k0 += 32) {
        #pragma unroll
        for (int rr = 0; rr < 2; rr++) {
            int f  = tid * 2 + rr;       // 0..511
            int m  = f >> 3;
            int kq = f & 7;
            float4 va = *reinterpret_cast<const float4*>(Ag + m * 3136 + k0 + kq * 4);
            float4 vb = *reinterpret_cast<const float4*>(Wg + m * 3136 + k0 + kq * 4);
            As[(kq * 4 + 0) * 65 + m] = va.x;
            As[(kq * 4 + 1) * 65 + m] = va.y;
            As[(kq * 4 + 2) * 65 + m] = va.z;
            As[(kq * 4 + 3) * 65 + m] = va.w;
            Bs[(kq * 4 + 0) * 65 + m] = vb.x;
            Bs[(kq * 4 + 1) * 65 + m] = vb.y;
            Bs[(kq * 4 + 2) * 65 + m] = vb.z;
            Bs[(kq * 4 + 3) * 65 + m] = vb.w;
        }
        __syncthreads();
        #pragma unroll 8
        for (int kk = 0; kk < 32; kk++) {
            float a[4], bf[4];
            #pragma unroll
            for (int i = 0; i < 4; i++) a[i]  = As[kk * 65 + ty * 4 + i];
            #pragma unroll
            for (int j = 0; j < 4; j++) bf[j] = Bs[kk * 65 + tx * 4 + j];
            #pragma unroll
            for (int i = 0; i < 4; i++)
                #pragma unroll
                for (int j = 0; j < 4; j++)
                    acc[i][j] += a[i] * bf[j];
        }
        __syncthreads();
    }

    #pragma unroll
    for (int i = 0; i < 4; i++) {
        int row = bm * 64 + ty * 4 + i;
        #pragma unroll
        for (int j = 0; j < 4; j++) {
            int col = bn * 64 + tx * 4 + j;
            float v = acc[i][j] + bias[col];
            g_h4[row * 512 + col] = fmaxf(v, 0.f);
        }
    }
}

// =====================================================================
// heads: out[k][b][a] = sum_d h4[b][d] * hw[k][d][a] + hb[k][a]
// Block = (head k, 512-row tile). Weights in smem padded [512][20].
// Thread: 2 rows x 20 (18 used) accumulators. h read from L2.
// =====================================================================
__global__ __launch_bounds__(256) void heads_kernel(
    const float* __restrict__ hw, const float* __restrict__ hb,
    float* __restrict__ out)
{
    __shared__ float w_s[512 * 20];

    const int k   = blockIdx.y;
    const int bt  = blockIdx.x;
    const int tid = threadIdx.x;

    const float* wg = hw + k * 9216;
    for (int idx = tid; idx < 512 * 20; idx += blockDim.x) {
        int d = idx / 20;
        int a = idx - d * 20;
        w_s[idx] = (a < 18) ? wg[d * 18 + a] : 0.f;
    }
    __syncthreads();

    const int b0 = bt * 512 + tid * 2;
    const float* h0p = g_h4 + b0 * 512;
    const float* h1p = h0p + 512;

    float acc[2][20];
    #pragma unroll
    for (int i = 0; i < 2; i++)
        #pragma unroll
        for (int a = 0; a < 20; a++) acc[i][a] = 0.f;

    for (int d = 0; d < 512; d += 4) {
        float ha0[4], ha1[4];
        *reinterpret_cast<float4*>(ha0) = *reinterpret_cast<const float4*>(h0p + d);
        *reinterpret_cast<float4*>(ha1) = *reinterpret_cast<const float4*>(h1p + d);
        #pragma unroll
        for (int dd = 0; dd < 4; dd++) {
            const float4* wp = reinterpret_cast<const float4*>(w_s + (d + dd) * 20);
            float4 w0 = wp[0], w1 = wp[1], w2 = wp[2], w3 = wp[3], w4 = wp[4];
            float a0 = ha0[dd], a1 = ha1[dd];
            acc[0][0]  += a0 * w0.x;  acc[0][1]  += a0 * w0.y;
            acc[0][2]  += a0 * w0.z;  acc[0][3]  += a0 * w0.w;
            acc[0][4]  += a0 * w1.x;  acc[0][5]  += a0 * w1.y;
            acc[0][6]  += a0 * w1.z;  acc[0][7]  += a0 * w1.w;
            acc[0][8]  += a0 * w2.x;  acc[0][9]  += a0 * w2.y;
            acc[0][10] += a0 * w2.z;  acc[0][11] += a0 * w2.w;
            acc[0][12] += a0 * w3.x;  acc[0][13] += a0 * w3.y;
            acc[0][14] += a0 * w3.z;  acc[0][15] += a0 * w3.w;
            acc[0][16] += a0 * w4.x;  acc[0][17] += a0 * w4.y;
            acc[0][18] += a0 * w4.z;  acc[0][19] += a0 * w4.w;
            acc[1][0]  += a1 * w0.x;  acc[1][1]  += a1 * w0.y;
            acc[1][2]  += a1 * w0.z;  acc[1][3]  += a1 * w0.w;
            acc[1][4]  += a1 * w1.x;  acc[1][5]  += a1 * w1.y;
            acc[1][6]  += a1 * w1.z;  acc[1][7]  += a1 * w1.w;
            acc[1][8]  += a1 * w2.x;  acc[1][9]  += a1 * w2.y;
            acc[1][10] += a1 * w2.z;  acc[1][11] += a1 * w2.w;
            acc[1][12] += a1 * w3.x;  acc[1][13] += a1 * w3.y;
            acc[1][14] += a1 * w3.z;  acc[1][15] += a1 * w3.w;
            acc[1][16] += a1 * w4.x;  acc[1][17] += a1 * w4.y;
            acc[1][18] += a1 * w4.z;  acc[1][19] += a1 * w4.w;
        }
    }

    #pragma unroll
    for (int i = 0; i < 2; i++) {
        float* ob = out + (k * 1024 + b0 + i) * 18;
        #pragma unroll
        for (int a = 0; a < 18; a++)
            ob[a] = acc[i][a] + hb[k * 18 + a];
    }
}

// =====================================================================
extern "C" void kernel_launch(void* const* d_in, const int* in_sizes, int n_in,
                              void* d_out, int out_size)
{
    const float* x   = (const float*)d_in[0];
    const float* c1w = (const float*)d_in[1];
    const float* c1b = (const float*)d_in[2];
    const float* c2w = (const float*)d_in[3];
    const float* c2b = (const float*)d_in[4];
    const float* c3w = (const float*)d_in[5];
    const float* c3b = (const float*)d_in[6];
    const float* l1w = (const float*)d_in[7];
    const float* l1b = (const float*)d_in[8];
    const float* hw  = (const float*)d_in[9];
    const float* hb  = (const float*)d_in[10];
    float* out = (float*)d_out;

    const int smem1 = (28224 + 8192) * 4;    // 145664
    const int smem2 = (12800 + 32768) * 4;   // 182272
    const int smem3 = (10400 + 36864) * 4;   // 189056
    cudaFuncSetAttribute(conv1_kernel, cudaFuncAttributeMaxDynamicSharedMemorySize, smem1);
    cudaFuncSetAttribute(conv2_kernel, cudaFuncAttributeMaxDynamicSharedMemorySize, smem2);
    cudaFuncSetAttribute(conv3_kernel, cudaFuncAttributeMaxDynamicSharedMemorySize, smem3);

    conv1_kernel<<<BATCH, 512, smem1>>>(x, c1w, c1b);
    conv2_kernel<<<BATCH, 256, smem2>>>(c2w, c2b);
    conv3_kernel<<<BATCH / 2, 256, smem3>>>(c3w, c3b);
    fc1_kernel<<<dim3(8, 16), 256>>>(l1w, l1b);
    heads_kernel<<<dim3(2, 200), 256>>>(hw, hb, out);
}